// round 3
// baseline (speedup 1.0000x reference)
#include <cuda_runtime.h>

// Problem constants
#define BB 32
#define NN 4096
#define DU 64
#define DD 128
#define CHUNKS 16
#define TPB 256              // tokens per block = NN/CHUNKS
#define TILE 32
#define NTILES (TPB / TILE)
#define NBLK (BB * CHUNKS)   // 512

typedef unsigned long long ull;

// Scratch (static __device__ — no allocations allowed)
__device__ float g_partG[NBLK][DD * DD];   // per-block Gram partials (33.5 MB)
__device__ float g_partS[NBLK][DD];        // per-block sum partials
__device__ float g_G[BB][DD * DD];         // reduced Gram per batch
__device__ float g_S[BB][DD];              // reduced sum per batch

// ---------------- packed fp32x2 helpers ----------------
__device__ __forceinline__ ull pack2(float lo, float hi) {
    ull r;
    asm("mov.b64 %0, {%1, %2};" : "=l"(r) : "f"(lo), "f"(hi));
    return r;
}
__device__ __forceinline__ void unpack2(ull v, float& lo, float& hi) {
    asm("mov.b64 {%0, %1}, %2;" : "=f"(lo), "=f"(hi) : "l"(v));
}
__device__ __forceinline__ void fma2(ull& d, ull a, ull b) {
    asm("fma.rn.f32x2 %0, %1, %2, %0;" : "+l"(d) : "l"(a), "l"(b));
}

// tanh-approx gelu (jax.nn.gelu default approximate=True)
// gelu(x) = 0.5 x (1 + tanh(sqrt(2/pi)(x + 0.044715 x^3)))
//         = x - x / (exp(2y) + 1),  2y = x*(1.59576912 + 0.07135482 x^2)
__device__ __forceinline__ float gelu_f(float x) {
    float x2 = x * x;
    float y2 = x * fmaf(0.0713548162f, x2, 1.5957691216f);
    float e  = __expf(y2);
    return x - __fdividef(x, e + 1.0f);
}

// ---------------- main fused kernel: MLP1 -> MLP2 -> Gram ----------------
__global__ void __launch_bounds__(256, 1)
fused_mlp_gram_kernel(const float* __restrict__ u,
                      const float* __restrict__ W1, const float* __restrict__ b1,
                      const float* __restrict__ W2, const float* __restrict__ b2)
{
    extern __shared__ float smf[];
    float* sW1 = smf;             // 64*128   = 8192
    float* sW2 = sW1 + 8192;      // 128*128  = 16384
    float* sU  = sW2 + 16384;     // 32*64    = 2048
    float* sZ1 = sU + 2048;       // 32*128   = 4096
    float* sZ  = sZ1 + 4096;      // 32*128   = 4096
    float* sB1 = sZ + 4096;       // 128
    float* sB2 = sB1 + 128;       // 128

    const int tid   = threadIdx.x;
    const int warp  = tid >> 5;
    const int lane  = tid & 31;
    const int c0    = lane << 2;   // 4 output cols per lane
    const int trow  = warp << 2;   // 4 tokens per warp (MLP phases)
    const int rbase = warp << 4;   // 16 Gram rows per warp

    // stage weights + biases into shared
    {
        const float4* w1v = (const float4*)W1;
        float4* s1 = (float4*)sW1;
#pragma unroll
        for (int i = 0; i < 8; i++) s1[tid + 256 * i] = w1v[tid + 256 * i];
        const float4* w2v = (const float4*)W2;
        float4* s2 = (float4*)sW2;
#pragma unroll
        for (int i = 0; i < 16; i++) s2[tid + 256 * i] = w2v[tid + 256 * i];
        if (tid < 128) { sB1[tid] = b1[tid]; sB2[tid] = b2[tid]; }
    }

    const int bidx  = blockIdx.x;
    const int batch = bidx / CHUNKS;
    const int chunk = bidx % CHUNKS;
    const float* ub = u + ((size_t)batch * NN + (size_t)chunk * TPB) * DU;

    // Gram accumulators: 8 row-pairs x 4 cols, packed (row r, row r+1) per ull
    ull gacc[8][4];
#pragma unroll
    for (int i = 0; i < 8; i++)
#pragma unroll
        for (int j = 0; j < 4; j++) gacc[i][j] = 0ull;
    float sac0 = 0.f, sac1 = 0.f, sac2 = 0.f, sac3 = 0.f;

    __syncthreads();

    for (int tt = 0; tt < NTILES; tt++) {
        // load u tile: 32 tokens x 64 = 2048 floats, contiguous
        {
            const float4* uv = (const float4*)(ub + tt * TILE * DU);
            float4* sUv = (float4*)sU;
            sUv[tid]       = uv[tid];
            sUv[tid + 256] = uv[tid + 256];
        }
        __syncthreads();

        // ---- MLP1: z1 = gelu(u @ W1 + b1) ----
        {
            ull acc[4][2];
            ull bi0 = pack2(sB1[c0],     sB1[c0 + 1]);
            ull bi1 = pack2(sB1[c0 + 2], sB1[c0 + 3]);
#pragma unroll
            for (int t = 0; t < 4; t++) { acc[t][0] = bi0; acc[t][1] = bi1; }
#pragma unroll 8
            for (int k = 0; k < DU; k++) {
                ulonglong2 w = *(const ulonglong2*)(sW1 + k * DD + c0);
#pragma unroll
                for (int t = 0; t < 4; t++) {
                    float us = sU[(trow + t) * DU + k];
                    ull ud = pack2(us, us);
                    fma2(acc[t][0], ud, w.x);
                    fma2(acc[t][1], ud, w.y);
                }
            }
#pragma unroll
            for (int t = 0; t < 4; t++) {
                float a, b_, c, d;
                unpack2(acc[t][0], a, b_);
                unpack2(acc[t][1], c, d);
                float4 r;
                r.x = gelu_f(a); r.y = gelu_f(b_); r.z = gelu_f(c); r.w = gelu_f(d);
                *(float4*)(sZ1 + (trow + t) * DD + c0) = r;
            }
        }
        __syncthreads();

        // ---- MLP2: z = gelu(z1 @ W2 + b2) ----
        {
            ull acc[4][2];
            ull bi0 = pack2(sB2[c0],     sB2[c0 + 1]);
            ull bi1 = pack2(sB2[c0 + 2], sB2[c0 + 3]);
#pragma unroll
            for (int t = 0; t < 4; t++) { acc[t][0] = bi0; acc[t][1] = bi1; }
#pragma unroll 8
            for (int k = 0; k < DD; k++) {
                ulonglong2 w = *(const ulonglong2*)(sW2 + k * DD + c0);
#pragma unroll
                for (int t = 0; t < 4; t++) {
                    float zs = sZ1[(trow + t) * DD + k];
                    ull zd = pack2(zs, zs);
                    fma2(acc[t][0], zd, w.x);
                    fma2(acc[t][1], zd, w.y);
                }
            }
#pragma unroll
            for (int t = 0; t < 4; t++) {
                float a, b_, c, d;
                unpack2(acc[t][0], a, b_);
                unpack2(acc[t][1], c, d);
                float4 r;
                r.x = gelu_f(a); r.y = gelu_f(b_); r.z = gelu_f(c); r.w = gelu_f(d);
                *(float4*)(sZ + (trow + t) * DD + c0) = r;
            }
        }
        __syncthreads();

        // ---- Gram: gacc += z_t (outer) z_t ; s += z_t ----
#pragma unroll 4
        for (int t = 0; t < TILE; t++) {
            const float* zrow = sZ + t * DD;
            ulonglong2 p0 = *(const ulonglong2*)(zrow + rbase);
            ulonglong2 p1 = *(const ulonglong2*)(zrow + rbase + 4);
            ulonglong2 p2 = *(const ulonglong2*)(zrow + rbase + 8);
            ulonglong2 p3 = *(const ulonglong2*)(zrow + rbase + 12);
            float4 zc = *(const float4*)(zrow + c0);
            ull d0 = pack2(zc.x, zc.x), d1 = pack2(zc.y, zc.y);
            ull d2 = pack2(zc.z, zc.z), d3 = pack2(zc.w, zc.w);
            ull zr[8] = { p0.x, p0.y, p1.x, p1.y, p2.x, p2.y, p3.x, p3.y };
#pragma unroll
            for (int rp = 0; rp < 8; rp++) {
                fma2(gacc[rp][0], zr[rp], d0);
                fma2(gacc[rp][1], zr[rp], d1);
                fma2(gacc[rp][2], zr[rp], d2);
                fma2(gacc[rp][3], zr[rp], d3);
            }
            if (warp == 0) { sac0 += zc.x; sac1 += zc.y; sac2 += zc.z; sac3 += zc.w; }
        }
        __syncthreads();
    }

    // write Gram partials (coalesced STG.128)
    float* gp = g_partG[bidx];
#pragma unroll
    for (int rp = 0; rp < 8; rp++) {
        float r0[4], r1[4];
#pragma unroll
        for (int c = 0; c < 4; c++) unpack2(gacc[rp][c], r0[c], r1[c]);
        *(float4*)(gp + (rbase + 2 * rp) * DD + c0)     = make_float4(r0[0], r0[1], r0[2], r0[3]);
        *(float4*)(gp + (rbase + 2 * rp + 1) * DD + c0) = make_float4(r1[0], r1[1], r1[2], r1[3]);
    }
    if (warp == 0)
        *(float4*)(g_partS[bidx] + c0) = make_float4(sac0, sac1, sac2, sac3);
}

// ---------------- reduce partials across chunks ----------------
__global__ void reduce_kernel()
{
    int idx = blockIdx.x * 256 + threadIdx.x;
    if (idx < BB * DD * DD) {
        int b = idx >> 14;         // /16384
        int cell = idx & 16383;
        float s = 0.f;
#pragma unroll
        for (int c = 0; c < CHUNKS; c++) s += g_partG[b * CHUNKS + c][cell];
        g_G[b][cell] = s;
    } else {
        int i2 = idx - BB * DD * DD;
        if (i2 < BB * DD) {
            int b = i2 >> 7, cell = i2 & 127;
            float s = 0.f;
#pragma unroll
            for (int c = 0; c < CHUNKS; c++) s += g_partS[b * CHUNKS + c][cell];
            g_S[b][cell] = s;
        }
    }
}

// ---------------- tail: factorized attention + output projection ----------------
// KᵀV = Wkᵀ G Wv + (Wkᵀ s) bvᵀ + bk (sᵀ Wv) + N bk bvᵀ
// out = (qᵀ context) @ Wo + bo  (per head, /N)
__global__ void tail_kernel(const float* __restrict__ embed,
                            const float* __restrict__ Wq, const float* __restrict__ bq,
                            const float* __restrict__ Wk, const float* __restrict__ bk,
                            const float* __restrict__ Wv, const float* __restrict__ bv,
                            const float* __restrict__ Wo, const float* __restrict__ bo,
                            float* __restrict__ out)
{
    __shared__ float semb[DD], sqf[DD], sa0[DD], sa1[DD], ss[DD], sm0[DD], sm1[DD], sattn[DD];
    const int t = threadIdx.x;   // 0..127
    const int b = blockIdx.x;    // 0..31

    semb[t] = embed[t];
    ss[t]   = g_S[b][t];
    __syncthreads();

    // qf = embed @ Wq + bq  (same for all batches)
    float acc = bq[t];
#pragma unroll 8
    for (int p = 0; p < DD; p++) acc = fmaf(semb[p], Wq[p * DD + t], acc);
    sqf[t] = acc;
    __syncthreads();

    // a_h[p] = sum_d qf[h*64+d] * Wk[p][h*64+d]
    float a0 = 0.f, a1 = 0.f;
#pragma unroll 8
    for (int d = 0; d < 64; d++) {
        a0 = fmaf(sqf[d],      Wk[t * DD + d],      a0);
        a1 = fmaf(sqf[64 + d], Wk[t * DD + 64 + d], a1);
    }
    sa0[t] = a0; sa1[t] = a1;
    __syncthreads();

    // m_h[q] = sum_p a_h[p] * G[p][q]
    const float* Gb = g_G[b];
    float m0 = 0.f, m1 = 0.f;
#pragma unroll 8
    for (int p = 0; p < DD; p++) {
        float g = Gb[p * DD + t];
        m0 = fmaf(sa0[p], g, m0);
        m1 = fmaf(sa1[p], g, m1);
    }
    sm0[t] = m0; sm1[t] = m1;
    __syncthreads();

    // scalars (redundant per-thread, cheap)
    float asd0 = 0.f, asd1 = 0.f;
#pragma unroll 8
    for (int p = 0; p < DD; p++) {
        asd0 = fmaf(sa0[p], ss[p], asd0);
        asd1 = fmaf(sa1[p], ss[p], asd1);
    }
    float qbk0 = 0.f, qbk1 = 0.f;
#pragma unroll 8
    for (int d = 0; d < 64; d++) {
        qbk0 = fmaf(sqf[d],      bk[d],      qbk0);
        qbk1 = fmaf(sqf[64 + d], bk[64 + d], qbk1);
    }

    // attn[t] (t = h*64 + e)
    const int h = t >> 6;
    const float* smh = h ? sm1 : sm0;
    float dotm = 0.f, swv = 0.f;
#pragma unroll 8
    for (int q = 0; q < DD; q++) {
        float w = Wv[q * DD + t];
        dotm = fmaf(smh[q], w, dotm);
        swv  = fmaf(ss[q],  w, swv);
    }
    float asd = h ? asd1 : asd0;
    float qbk = h ? qbk1 : qbk0;
    float attn = (dotm + asd * bv[t] + qbk * (swv + (float)NN * bv[t])) * (1.0f / (float)NN);
    sattn[t] = attn;
    __syncthreads();

    // out = attn @ Wo + bo
    float o = bo[t];
#pragma unroll 8
    for (int i = 0; i < DD; i++) o = fmaf(sattn[i], Wo[i * DD + t], o);
    out[b * DD + t] = o;
}

// ---------------- launch ----------------
extern "C" void kernel_launch(void* const* d_in, const int* in_sizes, int n_in,
                              void* d_out, int out_size)
{
    const float* u     = (const float*)d_in[0];
    // d_in[1] = x : unused by the reference
    const float* W1    = (const float*)d_in[2];
    const float* b1    = (const float*)d_in[3];
    const float* W2    = (const float*)d_in[4];
    const float* b2    = (const float*)d_in[5];
    const float* embed = (const float*)d_in[6];
    const float* Wq    = (const float*)d_in[7];
    const float* bq    = (const float*)d_in[8];
    const float* Wk    = (const float*)d_in[9];
    const float* bk    = (const float*)d_in[10];
    const float* Wv    = (const float*)d_in[11];
    const float* bv    = (const float*)d_in[12];
    const float* Wo    = (const float*)d_in[13];
    const float* bo    = (const float*)d_in[14];
    float* out = (float*)d_out;

    const int smem_bytes = (8192 + 16384 + 2048 + 4096 + 4096 + 128 + 128) * 4; // 140288 B
    cudaFuncSetAttribute(fused_mlp_gram_kernel,
                         cudaFuncAttributeMaxDynamicSharedMemorySize, smem_bytes);

    fused_mlp_gram_kernel<<<NBLK, 256, smem_bytes>>>(u, W1, b1, W2, b2);

    const int total = BB * DD * DD + BB * DD;
    reduce_kernel<<<(total + 255) / 256, 256>>>();

    tail_kernel<<<BB, 128>>>(embed, Wq, bq, Wk, bk, Wv, bv, Wo, bo, out);
}

// round 4
// speedup vs baseline: 1.0137x; 1.0137x over previous
#include <cuda_runtime.h>

// Problem constants
#define BB 32
#define NN 4096
#define DU 64
#define DD 128
#define CHUNKS 16
#define TPB 256              // tokens per block = NN/CHUNKS
#define TILE 32
#define NTILES (TPB / TILE)
#define NBLK (BB * CHUNKS)   // 512

typedef unsigned long long ull;

// Scratch (static __device__ — no allocations allowed)
__device__ float g_partG[NBLK][DD * DD];   // per-block Gram partials (33.5 MB)
__device__ float g_partS[NBLK][DD];        // per-block sum partials
__device__ float g_G[BB][DD * DD];         // reduced Gram per batch
__device__ float g_S[BB][DD];              // reduced sum per batch

// ---------------- packed fp32x2 helpers ----------------
__device__ __forceinline__ ull pack2(float lo, float hi) {
    ull r;
    asm("mov.b64 %0, {%1, %2};" : "=l"(r) : "f"(lo), "f"(hi));
    return r;
}
__device__ __forceinline__ void unpack2(ull v, float& lo, float& hi) {
    asm("mov.b64 {%0, %1}, %2;" : "=f"(lo), "=f"(hi) : "l"(v));
}
__device__ __forceinline__ void fma2(ull& d, ull a, ull b) {
    asm("fma.rn.f32x2 %0, %1, %2, %0;" : "+l"(d) : "l"(a), "l"(b));
}

// tanh-approx gelu (jax.nn.gelu default approximate=True)
// gelu(x) = 0.5 x (1 + tanh(sqrt(2/pi)(x + 0.044715 x^3)))
//         = x - x / (exp(2y) + 1),  2y = x*(1.59576912 + 0.07135482 x^2)
__device__ __forceinline__ float gelu_f(float x) {
    float x2 = x * x;
    float y2 = x * fmaf(0.0713548162f, x2, 1.5957691216f);
    float e  = __expf(y2);
    return x - __fdividef(x, e + 1.0f);
}

// ---------------- main fused kernel: MLP1 -> MLP2 -> Gram ----------------
__global__ void __launch_bounds__(256, 1)
fused_mlp_gram_kernel(const float* __restrict__ u,
                      const float* __restrict__ W1, const float* __restrict__ b1,
                      const float* __restrict__ W2, const float* __restrict__ b2)
{
    extern __shared__ float smf[];
    float* sW1 = smf;             // 64*128   = 8192
    float* sW2 = sW1 + 8192;      // 128*128  = 16384
    float* sU  = sW2 + 16384;     // 32*64    = 2048
    float* sZ1 = sU + 2048;       // 32*128   = 4096
    float* sZ  = sZ1 + 4096;      // 32*128   = 4096
    float* sB1 = sZ + 4096;       // 128
    float* sB2 = sB1 + 128;       // 128

    const int tid   = threadIdx.x;
    const int warp  = tid >> 5;
    const int lane  = tid & 31;
    const int c0    = lane << 2;   // 4 output cols per lane
    const int trow  = warp << 2;   // 4 tokens per warp (MLP phases)
    const int rbase = warp << 4;   // 16 Gram rows per warp

    // stage weights + biases into shared
    {
        const float4* w1v = (const float4*)W1;
        float4* s1 = (float4*)sW1;
#pragma unroll
        for (int i = 0; i < 8; i++) s1[tid + 256 * i] = w1v[tid + 256 * i];
        const float4* w2v = (const float4*)W2;
        float4* s2 = (float4*)sW2;
#pragma unroll
        for (int i = 0; i < 16; i++) s2[tid + 256 * i] = w2v[tid + 256 * i];
        if (tid < 128) { sB1[tid] = b1[tid]; sB2[tid] = b2[tid]; }
    }

    const int bidx  = blockIdx.x;
    const int batch = bidx / CHUNKS;
    const int chunk = bidx % CHUNKS;
    const float* ub = u + ((size_t)batch * NN + (size_t)chunk * TPB) * DU;

    // Gram accumulators: 8 row-pairs x 4 cols, packed (row r, row r+1) per ull
    ull gacc[8][4];
#pragma unroll
    for (int i = 0; i < 8; i++)
#pragma unroll
        for (int j = 0; j < 4; j++) gacc[i][j] = 0ull;
    float sac0 = 0.f, sac1 = 0.f, sac2 = 0.f, sac3 = 0.f;

    __syncthreads();

    for (int tt = 0; tt < NTILES; tt++) {
        // load u tile: 32 tokens x 64 = 2048 floats, contiguous
        {
            const float4* uv = (const float4*)(ub + tt * TILE * DU);
            float4* sUv = (float4*)sU;
            sUv[tid]       = uv[tid];
            sUv[tid + 256] = uv[tid + 256];
        }
        __syncthreads();

        // ---- MLP1: z1 = gelu(u @ W1 + b1) ----
        {
            ull acc[4][2];
            ull bi0 = pack2(sB1[c0],     sB1[c0 + 1]);
            ull bi1 = pack2(sB1[c0 + 2], sB1[c0 + 3]);
#pragma unroll
            for (int t = 0; t < 4; t++) { acc[t][0] = bi0; acc[t][1] = bi1; }
#pragma unroll 8
            for (int k = 0; k < DU; k++) {
                ulonglong2 w = *(const ulonglong2*)(sW1 + k * DD + c0);
#pragma unroll
                for (int t = 0; t < 4; t++) {
                    float us = sU[(trow + t) * DU + k];
                    ull ud = pack2(us, us);
                    fma2(acc[t][0], ud, w.x);
                    fma2(acc[t][1], ud, w.y);
                }
            }
#pragma unroll
            for (int t = 0; t < 4; t++) {
                float a, b_, c, d;
                unpack2(acc[t][0], a, b_);
                unpack2(acc[t][1], c, d);
                float4 r;
                r.x = gelu_f(a); r.y = gelu_f(b_); r.z = gelu_f(c); r.w = gelu_f(d);
                *(float4*)(sZ1 + (trow + t) * DD + c0) = r;
            }
        }
        __syncthreads();

        // ---- MLP2: z = gelu(z1 @ W2 + b2) ----
        {
            ull acc[4][2];
            ull bi0 = pack2(sB2[c0],     sB2[c0 + 1]);
            ull bi1 = pack2(sB2[c0 + 2], sB2[c0 + 3]);
#pragma unroll
            for (int t = 0; t < 4; t++) { acc[t][0] = bi0; acc[t][1] = bi1; }
#pragma unroll 8
            for (int k = 0; k < DD; k++) {
                ulonglong2 w = *(const ulonglong2*)(sW2 + k * DD + c0);
#pragma unroll
                for (int t = 0; t < 4; t++) {
                    float zs = sZ1[(trow + t) * DD + k];
                    ull zd = pack2(zs, zs);
                    fma2(acc[t][0], zd, w.x);
                    fma2(acc[t][1], zd, w.y);
                }
            }
#pragma unroll
            for (int t = 0; t < 4; t++) {
                float a, b_, c, d;
                unpack2(acc[t][0], a, b_);
                unpack2(acc[t][1], c, d);
                float4 r;
                r.x = gelu_f(a); r.y = gelu_f(b_); r.z = gelu_f(c); r.w = gelu_f(d);
                *(float4*)(sZ + (trow + t) * DD + c0) = r;
            }
        }
        __syncthreads();

        // ---- Gram: gacc += z_t (outer) z_t ; s += z_t ----
#pragma unroll 4
        for (int t = 0; t < TILE; t++) {
            const float* zrow = sZ + t * DD;
            ulonglong2 p0 = *(const ulonglong2*)(zrow + rbase);
            ulonglong2 p1 = *(const ulonglong2*)(zrow + rbase + 4);
            ulonglong2 p2 = *(const ulonglong2*)(zrow + rbase + 8);
            ulonglong2 p3 = *(const ulonglong2*)(zrow + rbase + 12);
            float4 zc = *(const float4*)(zrow + c0);
            ull d0 = pack2(zc.x, zc.x), d1 = pack2(zc.y, zc.y);
            ull d2 = pack2(zc.z, zc.z), d3 = pack2(zc.w, zc.w);
            ull zr[8] = { p0.x, p0.y, p1.x, p1.y, p2.x, p2.y, p3.x, p3.y };
#pragma unroll
            for (int rp = 0; rp < 8; rp++) {
                fma2(gacc[rp][0], zr[rp], d0);
                fma2(gacc[rp][1], zr[rp], d1);
                fma2(gacc[rp][2], zr[rp], d2);
                fma2(gacc[rp][3], zr[rp], d3);
            }
            if (warp == 0) { sac0 += zc.x; sac1 += zc.y; sac2 += zc.z; sac3 += zc.w; }
        }
        __syncthreads();
    }

    // write Gram partials (coalesced STG.128)
    float* gp = g_partG[bidx];
#pragma unroll
    for (int rp = 0; rp < 8; rp++) {
        float r0[4], r1[4];
#pragma unroll
        for (int c = 0; c < 4; c++) unpack2(gacc[rp][c], r0[c], r1[c]);
        *(float4*)(gp + (rbase + 2 * rp) * DD + c0)     = make_float4(r0[0], r0[1], r0[2], r0[3]);
        *(float4*)(gp + (rbase + 2 * rp + 1) * DD + c0) = make_float4(r1[0], r1[1], r1[2], r1[3]);
    }
    if (warp == 0)
        *(float4*)(g_partS[bidx] + c0) = make_float4(sac0, sac1, sac2, sac3);
}

// ---------------- reduce partials across chunks ----------------
__global__ void reduce_kernel()
{
    int idx = blockIdx.x * 256 + threadIdx.x;
    if (idx < BB * DD * DD) {
        int b = idx >> 14;         // /16384
        int cell = idx & 16383;
        float s = 0.f;
#pragma unroll
        for (int c = 0; c < CHUNKS; c++) s += g_partG[b * CHUNKS + c][cell];
        g_G[b][cell] = s;
    } else {
        int i2 = idx - BB * DD * DD;
        if (i2 < BB * DD) {
            int b = i2 >> 7, cell = i2 & 127;
            float s = 0.f;
#pragma unroll
            for (int c = 0; c < CHUNKS; c++) s += g_partS[b * CHUNKS + c][cell];
            g_S[b][cell] = s;
        }
    }
}

// ---------------- tail: factorized attention + output projection ----------------
// KᵀV = Wkᵀ G Wv + (Wkᵀ s) bvᵀ + bk (sᵀ Wv) + N bk bvᵀ
// out = (qᵀ context) @ Wo + bo  (per head, /N)
__global__ void tail_kernel(const float* __restrict__ embed,
                            const float* __restrict__ Wq, const float* __restrict__ bq,
                            const float* __restrict__ Wk, const float* __restrict__ bk,
                            const float* __restrict__ Wv, const float* __restrict__ bv,
                            const float* __restrict__ Wo, const float* __restrict__ bo,
                            float* __restrict__ out)
{
    __shared__ float semb[DD], sqf[DD], sa0[DD], sa1[DD], ss[DD], sm0[DD], sm1[DD], sattn[DD];
    const int t = threadIdx.x;   // 0..127
    const int b = blockIdx.x;    // 0..31

    semb[t] = embed[t];
    ss[t]   = g_S[b][t];
    __syncthreads();

    // qf = embed @ Wq + bq  (same for all batches)
    float acc = bq[t];
#pragma unroll 8
    for (int p = 0; p < DD; p++) acc = fmaf(semb[p], Wq[p * DD + t], acc);
    sqf[t] = acc;
    __syncthreads();

    // a_h[p] = sum_d qf[h*64+d] * Wk[p][h*64+d]
    float a0 = 0.f, a1 = 0.f;
#pragma unroll 8
    for (int d = 0; d < 64; d++) {
        a0 = fmaf(sqf[d],      Wk[t * DD + d],      a0);
        a1 = fmaf(sqf[64 + d], Wk[t * DD + 64 + d], a1);
    }
    sa0[t] = a0; sa1[t] = a1;
    __syncthreads();

    // m_h[q] = sum_p a_h[p] * G[p][q]
    const float* Gb = g_G[b];
    float m0 = 0.f, m1 = 0.f;
#pragma unroll 8
    for (int p = 0; p < DD; p++) {
        float g = Gb[p * DD + t];
        m0 = fmaf(sa0[p], g, m0);
        m1 = fmaf(sa1[p], g, m1);
    }
    sm0[t] = m0; sm1[t] = m1;
    __syncthreads();

    // scalars (redundant per-thread, cheap)
    float asd0 = 0.f, asd1 = 0.f;
#pragma unroll 8
    for (int p = 0; p < DD; p++) {
        asd0 = fmaf(sa0[p], ss[p], asd0);
        asd1 = fmaf(sa1[p], ss[p], asd1);
    }
    float qbk0 = 0.f, qbk1 = 0.f;
#pragma unroll 8
    for (int d = 0; d < 64; d++) {
        qbk0 = fmaf(sqf[d],      bk[d],      qbk0);
        qbk1 = fmaf(sqf[64 + d], bk[64 + d], qbk1);
    }

    // attn[t] (t = h*64 + e)
    const int h = t >> 6;
    const float* smh = h ? sm1 : sm0;
    float dotm = 0.f, swv = 0.f;
#pragma unroll 8
    for (int q = 0; q < DD; q++) {
        float w = Wv[q * DD + t];
        dotm = fmaf(smh[q], w, dotm);
        swv  = fmaf(ss[q],  w, swv);
    }
    float asd = h ? asd1 : asd0;
    float qbk = h ? qbk1 : qbk0;
    float attn = (dotm + asd * bv[t] + qbk * (swv + (float)NN * bv[t])) * (1.0f / (float)NN);
    sattn[t] = attn;
    __syncthreads();

    // out = attn @ Wo + bo
    float o = bo[t];
#pragma unroll 8
    for (int i = 0; i < DD; i++) o = fmaf(sattn[i], Wo[i * DD + t], o);
    out[b * DD + t] = o;
}

// ---------------- launch ----------------
extern "C" void kernel_launch(void* const* d_in, const int* in_sizes, int n_in,
                              void* d_out, int out_size)
{
    const float* u     = (const float*)d_in[0];
    // d_in[1] = x : unused by the reference
    const float* W1    = (const float*)d_in[2];
    const float* b1    = (const float*)d_in[3];
    const float* W2    = (const float*)d_in[4];
    const float* b2    = (const float*)d_in[5];
    const float* embed = (const float*)d_in[6];
    const float* Wq    = (const float*)d_in[7];
    const float* bq    = (const float*)d_in[8];
    const float* Wk    = (const float*)d_in[9];
    const float* bk    = (const float*)d_in[10];
    const float* Wv    = (const float*)d_in[11];
    const float* bv    = (const float*)d_in[12];
    const float* Wo    = (const float*)d_in[13];
    const float* bo    = (const float*)d_in[14];
    float* out = (float*)d_out;

    const int smem_bytes = (8192 + 16384 + 2048 + 4096 + 4096 + 128 + 128) * 4; // 140288 B
    cudaFuncSetAttribute(fused_mlp_gram_kernel,
                         cudaFuncAttributeMaxDynamicSharedMemorySize, smem_bytes);

    fused_mlp_gram_kernel<<<NBLK, 256, smem_bytes>>>(u, W1, b1, W2, b2);

    const int total = BB * DD * DD + BB * DD;
    reduce_kernel<<<(total + 255) / 256, 256>>>();

    tail_kernel<<<BB, 128>>>(embed, Wq, bq, Wk, bk, Wv, bv, Wo, bo, out);
}

// round 6
// speedup vs baseline: 2.2990x; 2.2680x over previous
#include <cuda_runtime.h>
#include <cstdint>

#define BB 32
#define NN 4096
#define DU 64
#define DD 128
#define TILES 8
#define CHUNKS 4
#define NBLK (BB*CHUNKS)     // 128 blocks, single wave

// shared-memory layout (float offsets)
#define W1_O 0                       // [64][132]
#define W2_O (W1_O + 64*132)         // [128][132]
#define U_O  (W2_O + 128*132)        // [128][68]
#define Z_O  (U_O  + 128*68)         // [128][132]  (Z1 then Z, aliased)
#define B1_O (Z_O  + 128*132)
#define B2_O (B1_O + 128)
#define SS_O (B2_O + 128)
#define SMEM_FLOATS (SS_O + 128)
#define SMEM_BYTES (SMEM_FLOATS * 4) // 205,312 B

__device__ float g_partG[NBLK][DD*DD];
__device__ float g_partS[NBLK][DD];

static __device__ __forceinline__ uint32_t tf32r(float f) {
    uint32_t r; asm("cvt.rna.tf32.f32 %0, %1;" : "=r"(r) : "f"(f)); return r;
}
static __device__ __forceinline__ float tf32f(float f) {
    return __uint_as_float(tf32r(f));
}
// jax.nn.gelu approximate (validated rel_err 3.7e-7 in fp32 kernel)
static __device__ __forceinline__ float gelu_f(float x) {
    float x2 = x * x;
    float y2 = x * fmaf(0.0713548162f, x2, 1.5957691216f);
    float e  = __expf(y2);
    return x - __fdividef(x, e + 1.0f);
}
// m16n8k8 tf32 HMMA, D = A*B + D
static __device__ __forceinline__ void mma8(float* c, const uint32_t* a, const uint32_t* b) {
    asm volatile(
        "mma.sync.aligned.m16n8k8.row.col.f32.tf32.tf32.f32 "
        "{%0,%1,%2,%3},{%4,%5,%6,%7},{%8,%9},{%0,%1,%2,%3};"
        : "+f"(c[0]), "+f"(c[1]), "+f"(c[2]), "+f"(c[3])
        : "r"(a[0]), "r"(a[1]), "r"(a[2]), "r"(a[3]), "r"(b[0]), "r"(b[1]));
}

// ================= main fused kernel =================
__global__ void __launch_bounds__(256, 1)
fused_mma_kernel(const float* __restrict__ u,
                 const float* __restrict__ W1, const float* __restrict__ b1,
                 const float* __restrict__ W2, const float* __restrict__ b2)
{
    extern __shared__ float sm[];
    const int tid  = threadIdx.x;
    const int w    = tid >> 5;
    const int lane = tid & 31;
    const int lr   = lane >> 2;      // fragment row group 0..7
    const int lc   = lane & 3;       // fragment k group 0..3
    const int mb   = (w >> 1) * 32;  // warp row base (tokens / Gram rows)
    const int nb   = (w & 1) * 64;   // warp col base

    // ---- stage weights as tf32 ----
    for (int i = tid; i < 64 * 128; i += 256) {
        int k = i >> 7, n = i & 127;
        sm[W1_O + k * 132 + n] = tf32f(W1[i]);
    }
    for (int i = tid; i < 128 * 128; i += 256) {
        int k = i >> 7, n = i & 127;
        sm[W2_O + k * 132 + n] = tf32f(W2[i]);
    }
    if (tid < 128) { sm[B1_O + tid] = b1[tid]; sm[B2_O + tid] = b2[tid]; sm[SS_O + tid] = 0.f; }

    // per-thread bias values for the 16 columns this thread owns
    float b1r[16], b2r[16];
#pragma unroll
    for (int nt = 0; nt < 8; nt++) {
        int col = nb + nt * 8 + 2 * lc;
        // note: biases staged above by this block; safe to read after first sync
        b1r[nt * 2]     = 0.f; b1r[nt * 2 + 1] = 0.f;  // placeholder, filled after sync
        b2r[nt * 2]     = 0.f; b2r[nt * 2 + 1] = 0.f;
        (void)col;
    }

    float g[2][8][4];     // Gram accumulators (persist across tiles)
#pragma unroll
    for (int mt = 0; mt < 2; mt++)
#pragma unroll
        for (int nt = 0; nt < 8; nt++)
#pragma unroll
            for (int i = 0; i < 4; i++) g[mt][nt][i] = 0.f;
    float sacc[16];
#pragma unroll
    for (int i = 0; i < 16; i++) sacc[i] = 0.f;

    const int bid = blockIdx.x;
    const float* ub = u + ((size_t)(bid >> 2) * NN + (size_t)(bid & 3) * 1024) * DU;

    __syncthreads();

    // now biases are staged; load per-thread copies
#pragma unroll
    for (int nt = 0; nt < 8; nt++) {
        int col = nb + nt * 8 + 2 * lc;
        b1r[nt * 2] = sm[B1_O + col]; b1r[nt * 2 + 1] = sm[B1_O + col + 1];
        b2r[nt * 2] = sm[B2_O + col]; b2r[nt * 2 + 1] = sm[B2_O + col + 1];
    }

    for (int tt = 0; tt < TILES; tt++) {
        // ---- load U tile (128 tok x 64) as tf32, pitch 68 ----
        {
            const float4* uv = (const float4*)(ub + (size_t)tt * 128 * DU);
#pragma unroll
            for (int i = 0; i < 8; i++) {
                int idx = i * 256 + tid;
                int tok = idx >> 4, kq = idx & 15;
                float4 f = uv[idx];
                *(float4*)&sm[U_O + tok * 68 + kq * 4] =
                    make_float4(tf32f(f.x), tf32f(f.y), tf32f(f.z), tf32f(f.w));
            }
        }
        __syncthreads();

        float c[2][8][4];

        // ======== MLP1: C = U @ W1  (K=64) ========
#pragma unroll
        for (int mt = 0; mt < 2; mt++)
#pragma unroll
            for (int nt = 0; nt < 8; nt++)
#pragma unroll
                for (int i = 0; i < 4; i++) c[mt][nt][i] = 0.f;
        {
            const float* As = &sm[U_O + (mb + lr) * 68 + lc];
            const float* Bs = &sm[W1_O + lc * 132 + nb + lr];
#pragma unroll 4
            for (int kt = 0; kt < 8; kt++) {
                uint32_t a[2][4], bf[8][2];
#pragma unroll
                for (int mt = 0; mt < 2; mt++) {
                    const float* p = As + mt * 16 * 68 + kt * 8;
                    a[mt][0] = __float_as_uint(p[0]);
                    a[mt][1] = __float_as_uint(p[8 * 68]);
                    a[mt][2] = __float_as_uint(p[4]);
                    a[mt][3] = __float_as_uint(p[8 * 68 + 4]);
                }
#pragma unroll
                for (int nt = 0; nt < 8; nt++) {
                    const float* p = Bs + kt * 8 * 132 + nt * 8;
                    bf[nt][0] = __float_as_uint(p[0]);
                    bf[nt][1] = __float_as_uint(p[4 * 132]);
                }
#pragma unroll
                for (int mt = 0; mt < 2; mt++)
#pragma unroll
                    for (int nt = 0; nt < 8; nt++) mma8(c[mt][nt], a[mt], bf[nt]);
            }
        }
        __syncthreads();   // prev-tile Gram reads of Z done (loop-end sync) — safe to write Z1

        // epilogue 1: Z1 = gelu(C + b1) -> Z buffer (tf32)
#pragma unroll
        for (int mt = 0; mt < 2; mt++)
#pragma unroll
            for (int nt = 0; nt < 8; nt++) {
                int row = mb + mt * 16 + lr;
                int col = nb + nt * 8 + 2 * lc;
                float z0 = gelu_f(c[mt][nt][0] + b1r[nt * 2]);
                float z1 = gelu_f(c[mt][nt][1] + b1r[nt * 2 + 1]);
                float z2 = gelu_f(c[mt][nt][2] + b1r[nt * 2]);
                float z3 = gelu_f(c[mt][nt][3] + b1r[nt * 2 + 1]);
                *(float2*)&sm[Z_O + row * 132 + col]       = make_float2(tf32f(z0), tf32f(z1));
                *(float2*)&sm[Z_O + (row + 8) * 132 + col] = make_float2(tf32f(z2), tf32f(z3));
            }
        __syncthreads();

        // ======== MLP2: C = Z1 @ W2  (K=128) ========
#pragma unroll
        for (int mt = 0; mt < 2; mt++)
#pragma unroll
            for (int nt = 0; nt < 8; nt++)
#pragma unroll
                for (int i = 0; i < 4; i++) c[mt][nt][i] = 0.f;
        {
            const float* As = &sm[Z_O + (mb + lr) * 132 + lc];
            const float* Bs = &sm[W2_O + lc * 132 + nb + lr];
#pragma unroll 4
            for (int kt = 0; kt < 16; kt++) {
                uint32_t a[2][4], bf[8][2];
#pragma unroll
                for (int mt = 0; mt < 2; mt++) {
                    const float* p = As + mt * 16 * 132 + kt * 8;
                    a[mt][0] = __float_as_uint(p[0]);
                    a[mt][1] = __float_as_uint(p[8 * 132]);
                    a[mt][2] = __float_as_uint(p[4]);
                    a[mt][3] = __float_as_uint(p[8 * 132 + 4]);
                }
#pragma unroll
                for (int nt = 0; nt < 8; nt++) {
                    const float* p = Bs + kt * 8 * 132 + nt * 8;
                    bf[nt][0] = __float_as_uint(p[0]);
                    bf[nt][1] = __float_as_uint(p[4 * 132]);
                }
#pragma unroll
                for (int mt = 0; mt < 2; mt++)
#pragma unroll
                    for (int nt = 0; nt < 8; nt++) mma8(c[mt][nt], a[mt], bf[nt]);
            }
        }
        __syncthreads();   // all reads of Z1 complete before overwrite

        // epilogue 2: Z = gelu(C + b2) -> Z buffer; S += columns
#pragma unroll
        for (int mt = 0; mt < 2; mt++)
#pragma unroll
            for (int nt = 0; nt < 8; nt++) {
                int row = mb + mt * 16 + lr;
                int col = nb + nt * 8 + 2 * lc;
                float z0 = gelu_f(c[mt][nt][0] + b2r[nt * 2]);
                float z1 = gelu_f(c[mt][nt][1] + b2r[nt * 2 + 1]);
                float z2 = gelu_f(c[mt][nt][2] + b2r[nt * 2]);
                float z3 = gelu_f(c[mt][nt][3] + b2r[nt * 2 + 1]);
                sacc[nt * 2]     += z0 + z2;
                sacc[nt * 2 + 1] += z1 + z3;
                *(float2*)&sm[Z_O + row * 132 + col]       = make_float2(tf32f(z0), tf32f(z1));
                *(float2*)&sm[Z_O + (row + 8) * 132 + col] = make_float2(tf32f(z2), tf32f(z3));
            }
        __syncthreads();

        // ======== Gram: G += Z^T @ Z  (K = 128 tokens) ========
        {
            // A(m,k=t) = Z[t][m];  B(n,k=t) = Z[t][n]
#pragma unroll 4
            for (int kt = 0; kt < 16; kt++) {
                uint32_t a[2][4], bf[8][2];
                const float* At = &sm[Z_O + (kt * 8 + lc) * 132 + mb + lr];
#pragma unroll
                for (int mt = 0; mt < 2; mt++) {
                    const float* p = At + mt * 16;
                    a[mt][0] = __float_as_uint(p[0]);
                    a[mt][1] = __float_as_uint(p[8]);
                    a[mt][2] = __float_as_uint(p[4 * 132]);
                    a[mt][3] = __float_as_uint(p[4 * 132 + 8]);
                }
                const float* Bt = &sm[Z_O + (kt * 8 + lc) * 132 + nb + lr];
#pragma unroll
                for (int nt = 0; nt < 8; nt++) {
                    const float* p = Bt + nt * 8;
                    bf[nt][0] = __float_as_uint(p[0]);
                    bf[nt][1] = __float_as_uint(p[4 * 132]);
                }
#pragma unroll
                for (int mt = 0; mt < 2; mt++)
#pragma unroll
                    for (int nt = 0; nt < 8; nt++) mma8(g[mt][nt], a[mt], bf[nt]);
            }
        }
        __syncthreads();   // Gram reads done before next tile's Z1 write
    }

    // ---- stage G into Z buffer, then coalesced store ----
#pragma unroll
    for (int mt = 0; mt < 2; mt++)
#pragma unroll
        for (int nt = 0; nt < 8; nt++) {
            int row = mb + mt * 16 + lr;
            int col = nb + nt * 8 + 2 * lc;
            *(float2*)&sm[Z_O + row * 132 + col]       = make_float2(g[mt][nt][0], g[mt][nt][1]);
            *(float2*)&sm[Z_O + (row + 8) * 132 + col] = make_float2(g[mt][nt][2], g[mt][nt][3]);
        }
    __syncthreads();
    {
        float* gp = g_partG[bid];
#pragma unroll
        for (int i = 0; i < 16; i++) {
            int idx = i * 256 + tid;          // 4096 float4
            int r = idx >> 5, cq = idx & 31;
            ((float4*)gp)[idx] = *(const float4*)&sm[Z_O + r * 132 + cq * 4];
        }
    }

    // ---- reduce S: shfl over row groups, atomic into smem, store ----
    {
#pragma unroll
        for (int i = 0; i < 16; i++) {
            float v = sacc[i];
            v += __shfl_down_sync(0xFFFFFFFFu, v, 16);
            v += __shfl_down_sync(0xFFFFFFFFu, v, 8);
            v += __shfl_down_sync(0xFFFFFFFFu, v, 4);
            if (lr == 0) atomicAdd(&sm[SS_O + nb + (i >> 1) * 8 + 2 * lc + (i & 1)], v);
        }
        __syncthreads();
        if (tid < 128) g_partS[bid][tid] = sm[SS_O + tid];
    }
}

// ================= tail: reduce partials + factorized attention =================
__global__ void tail_kernel(const float* __restrict__ embed,
                            const float* __restrict__ Wq, const float* __restrict__ bq,
                            const float* __restrict__ Wk, const float* __restrict__ bk,
                            const float* __restrict__ Wv, const float* __restrict__ bv,
                            const float* __restrict__ Wo, const float* __restrict__ bo,
                            float* __restrict__ out)
{
    __shared__ float semb[DD], sqf[DD], sa0[DD], sa1[DD], ss[DD], sm0[DD], sm1[DD], sattn[DD];
    const int t = threadIdx.x;
    const int b = blockIdx.x;

    semb[t] = embed[t];
    ss[t] = g_partS[b*4][t] + g_partS[b*4+1][t] + g_partS[b*4+2][t] + g_partS[b*4+3][t];
    __syncthreads();

    float acc = bq[t];
#pragma unroll 8
    for (int p = 0; p < DD; p++) acc = fmaf(semb[p], Wq[p * DD + t], acc);
    sqf[t] = acc;
    __syncthreads();

    float a0 = 0.f, a1 = 0.f;
#pragma unroll 8
    for (int d = 0; d < 64; d++) {
        a0 = fmaf(sqf[d],      Wk[t * DD + d],      a0);
        a1 = fmaf(sqf[64 + d], Wk[t * DD + 64 + d], a1);
    }
    sa0[t] = a0; sa1[t] = a1;
    __syncthreads();

    const float* g0 = g_partG[b*4];
    const float* g1 = g_partG[b*4+1];
    const float* g2 = g_partG[b*4+2];
    const float* g3 = g_partG[b*4+3];
    float m0 = 0.f, m1 = 0.f;
#pragma unroll 8
    for (int p = 0; p < DD; p++) {
        float gv = g0[p * DD + t] + g1[p * DD + t] + g2[p * DD + t] + g3[p * DD + t];
        m0 = fmaf(sa0[p], gv, m0);
        m1 = fmaf(sa1[p], gv, m1);
    }
    sm0[t] = m0; sm1[t] = m1;
    __syncthreads();

    float asd0 = 0.f, asd1 = 0.f;
#pragma unroll 8
    for (int p = 0; p < DD; p++) {
        asd0 = fmaf(sa0[p], ss[p], asd0);
        asd1 = fmaf(sa1[p], ss[p], asd1);
    }
    float qbk0 = 0.f, qbk1 = 0.f;
#pragma unroll 8
    for (int d = 0; d < 64; d++) {
        qbk0 = fmaf(sqf[d],      bk[d],      qbk0);
        qbk1 = fmaf(sqf[64 + d], bk[64 + d], qbk1);
    }

    const int h = t >> 6;
    const float* smh = h ? sm1 : sm0;
    float dotm = 0.f, swv = 0.f;
#pragma unroll 8
    for (int q = 0; q < DD; q++) {
        float wv = Wv[q * DD + t];
        dotm = fmaf(smh[q], wv, dotm);
        swv  = fmaf(ss[q],  wv, swv);
    }
    float asd = h ? asd1 : asd0;
    float qbk = h ? qbk1 : qbk0;
    float attn = (dotm + asd * bv[t] + qbk * (swv + (float)NN * bv[t])) * (1.0f / (float)NN);
    sattn[t] = attn;
    __syncthreads();

    float o = bo[t];
#pragma unroll 8
    for (int i = 0; i < DD; i++) o = fmaf(sattn[i], Wo[i * DD + t], o);
    out[b * DD + t] = o;
}

// ================= launch =================
extern "C" void kernel_launch(void* const* d_in, const int* in_sizes, int n_in,
                              void* d_out, int out_size)
{
    const float* u     = (const float*)d_in[0];
    const float* W1    = (const float*)d_in[2];
    const float* b1    = (const float*)d_in[3];
    const float* W2    = (const float*)d_in[4];
    const float* b2    = (const float*)d_in[5];
    const float* embed = (const float*)d_in[6];
    const float* Wq    = (const float*)d_in[7];
    const float* bq    = (const float*)d_in[8];
    const float* Wk    = (const float*)d_in[9];
    const float* bk    = (const float*)d_in[10];
    const float* Wv    = (const float*)d_in[11];
    const float* bv    = (const float*)d_in[12];
    const float* Wo    = (const float*)d_in[13];
    const float* bo    = (const float*)d_in[14];
    float* out = (float*)d_out;

    cudaFuncSetAttribute(fused_mma_kernel,
                         cudaFuncAttributeMaxDynamicSharedMemorySize, SMEM_BYTES);

    fused_mma_kernel<<<NBLK, 256, SMEM_BYTES>>>(u, W1, b1, W2, b2);
    tail_kernel<<<BB, 128>>>(embed, Wq, bq, Wk, bk, Wv, bv, Wo, bo, out);
}

// round 7
// speedup vs baseline: 2.3215x; 1.0098x over previous
#include <cuda_runtime.h>
#include <cstdint>

#define BB 32
#define NN 4096
#define DU 64
#define DD 128
#define TILES 8
#define CHUNKS 4
#define NBLK (BB*CHUNKS)     // 128 blocks, single wave

// shared-memory layout (float offsets)
#define W1_O 0                       // [64][132]
#define W2_O (W1_O + 64*132)         // [128][132]
#define U_O  (W2_O + 128*132)        // [128][68]
#define Z_O  (U_O  + 128*68)         // [128][132]  (Z1 then Z, aliased)
#define B1_O (Z_O  + 128*132)
#define B2_O (B1_O + 128)
#define SS_O (B2_O + 128)
#define SQF_O (SS_O + 128)
#define SA0_O (SQF_O + 128)
#define SA1_O (SA0_O + 128)
#define SV_O  (SA1_O + 128)          // 256 floats: v0[128], v1[128]
#define SMEM_FLOATS (SV_O + 256)
#define SMEM_BYTES (SMEM_FLOATS * 4) // ~207.9 KB

__device__ float g_partV[NBLK][256];   // per-block a^T G partials (2 heads x 128)
__device__ float g_partS[NBLK][DD];

static __device__ __forceinline__ uint32_t tf32r(float f) {
    uint32_t r; asm("cvt.rna.tf32.f32 %0, %1;" : "=r"(r) : "f"(f)); return r;
}
static __device__ __forceinline__ float tf32f(float f) {
    return __uint_as_float(tf32r(f));
}
// jax.nn.gelu approximate
static __device__ __forceinline__ float gelu_f(float x) {
    float x2 = x * x;
    float y2 = x * fmaf(0.0713548162f, x2, 1.5957691216f);
    float e  = __expf(y2);
    return x - __fdividef(x, e + 1.0f);
}
// m16n8k8 tf32 HMMA, D = A*B + D
static __device__ __forceinline__ void mma8(float* c, const uint32_t* a, const uint32_t* b) {
    asm volatile(
        "mma.sync.aligned.m16n8k8.row.col.f32.tf32.tf32.f32 "
        "{%0,%1,%2,%3},{%4,%5,%6,%7},{%8,%9},{%0,%1,%2,%3};"
        : "+f"(c[0]), "+f"(c[1]), "+f"(c[2]), "+f"(c[3])
        : "r"(a[0]), "r"(a[1]), "r"(a[2]), "r"(a[3]), "r"(b[0]), "r"(b[1]));
}

// ================= main fused kernel =================
__global__ void __launch_bounds__(256, 1)
fused_mma_kernel(const float* __restrict__ u,
                 const float* __restrict__ W1, const float* __restrict__ b1,
                 const float* __restrict__ W2, const float* __restrict__ b2,
                 const float* __restrict__ embed,
                 const float* __restrict__ Wq, const float* __restrict__ bq,
                 const float* __restrict__ Wk)
{
    extern __shared__ float sm[];
    const int tid  = threadIdx.x;
    const int w    = tid >> 5;
    const int lane = tid & 31;
    const int lr   = lane >> 2;      // fragment row group 0..7
    const int lc   = lane & 3;       // fragment k group 0..3
    const int mb   = (w >> 1) * 32;  // warp row base
    const int nb   = (w & 1) * 64;   // warp col base

    // ---- stage weights as tf32 ----
    for (int i = tid; i < 64 * 128; i += 256) {
        int k = i >> 7, n = i & 127;
        sm[W1_O + k * 132 + n] = tf32f(W1[i]);
    }
    for (int i = tid; i < 128 * 128; i += 256) {
        int k = i >> 7, n = i & 127;
        sm[W2_O + k * 132 + n] = tf32f(W2[i]);
    }
    if (tid < 128) {
        sm[B1_O + tid] = b1[tid]; sm[B2_O + tid] = b2[tid];
        sm[SS_O + tid] = 0.f;
        sm[SV_O + tid] = 0.f; sm[SV_O + 128 + tid] = 0.f;
        // qf[t] = embed @ Wq + bq (identical across blocks; L2-broadcast reads)
        float acc = bq[tid];
#pragma unroll 8
        for (int p = 0; p < DD; p++) acc = fmaf(embed[p], Wq[p * DD + tid], acc);
        sm[SQF_O + tid] = acc;
    }

    float g[2][8][4];     // Gram accumulators
#pragma unroll
    for (int mt = 0; mt < 2; mt++)
#pragma unroll
        for (int nt = 0; nt < 8; nt++)
#pragma unroll
            for (int i = 0; i < 4; i++) g[mt][nt][i] = 0.f;
    float sacc[16];
#pragma unroll
    for (int i = 0; i < 16; i++) sacc[i] = 0.f;

    const int bid = blockIdx.x;
    const float* ub = u + ((size_t)(bid >> 2) * NN + (size_t)(bid & 3) * 1024) * DU;

    __syncthreads();

    // a_h[p] = sum_d qf[h*64+d] * Wk[p][h*64+d]  (visibility covered by later syncs)
    if (tid < 128) {
        float a0 = 0.f, a1 = 0.f;
#pragma unroll 8
        for (int d = 0; d < 64; d++) {
            a0 = fmaf(sm[SQF_O + d],      Wk[tid * DD + d],      a0);
            a1 = fmaf(sm[SQF_O + 64 + d], Wk[tid * DD + 64 + d], a1);
        }
        sm[SA0_O + tid] = a0; sm[SA1_O + tid] = a1;
    }

    float b1r[16], b2r[16];
#pragma unroll
    for (int nt = 0; nt < 8; nt++) {
        int col = nb + nt * 8 + 2 * lc;
        b1r[nt * 2] = sm[B1_O + col]; b1r[nt * 2 + 1] = sm[B1_O + col + 1];
        b2r[nt * 2] = sm[B2_O + col]; b2r[nt * 2 + 1] = sm[B2_O + col + 1];
    }

    // prefetch tile 0 into registers
    float4 pref[8];
    {
        const float4* uv = (const float4*)ub;
#pragma unroll
        for (int i = 0; i < 8; i++) pref[i] = uv[i * 256 + tid];
    }

    for (int tt = 0; tt < TILES; tt++) {
        // ---- store prefetched U tile (tf32, pitch 68), then prefetch next ----
#pragma unroll
        for (int i = 0; i < 8; i++) {
            int idx = i * 256 + tid;
            int tok = idx >> 4, kq = idx & 15;
            float4 f = pref[i];
            *(float4*)&sm[U_O + tok * 68 + kq * 4] =
                make_float4(tf32f(f.x), tf32f(f.y), tf32f(f.z), tf32f(f.w));
        }
        if (tt + 1 < TILES) {
            const float4* uv = (const float4*)(ub + (size_t)(tt + 1) * 128 * DU);
#pragma unroll
            for (int i = 0; i < 8; i++) pref[i] = uv[i * 256 + tid];
        }
        __syncthreads();

        float c[2][8][4];

        // ======== MLP1: C = U @ W1  (K=64) ========
#pragma unroll
        for (int mt = 0; mt < 2; mt++)
#pragma unroll
            for (int nt = 0; nt < 8; nt++)
#pragma unroll
                for (int i = 0; i < 4; i++) c[mt][nt][i] = 0.f;
        {
            const float* As = &sm[U_O + (mb + lr) * 68 + lc];
            const float* Bs = &sm[W1_O + lc * 132 + nb + lr];
#pragma unroll 4
            for (int kt = 0; kt < 8; kt++) {
                uint32_t a[2][4], bf[8][2];
#pragma unroll
                for (int mt = 0; mt < 2; mt++) {
                    const float* p = As + mt * 16 * 68 + kt * 8;
                    a[mt][0] = __float_as_uint(p[0]);
                    a[mt][1] = __float_as_uint(p[8 * 68]);
                    a[mt][2] = __float_as_uint(p[4]);
                    a[mt][3] = __float_as_uint(p[8 * 68 + 4]);
                }
#pragma unroll
                for (int nt = 0; nt < 8; nt++) {
                    const float* p = Bs + kt * 8 * 132 + nt * 8;
                    bf[nt][0] = __float_as_uint(p[0]);
                    bf[nt][1] = __float_as_uint(p[4 * 132]);
                }
#pragma unroll
                for (int mt = 0; mt < 2; mt++)
#pragma unroll
                    for (int nt = 0; nt < 8; nt++) mma8(c[mt][nt], a[mt], bf[nt]);
            }
        }
        __syncthreads();

        // epilogue 1: Z1 = gelu(C + b1)
#pragma unroll
        for (int mt = 0; mt < 2; mt++)
#pragma unroll
            for (int nt = 0; nt < 8; nt++) {
                int row = mb + mt * 16 + lr;
                int col = nb + nt * 8 + 2 * lc;
                float z0 = gelu_f(c[mt][nt][0] + b1r[nt * 2]);
                float z1 = gelu_f(c[mt][nt][1] + b1r[nt * 2 + 1]);
                float z2 = gelu_f(c[mt][nt][2] + b1r[nt * 2]);
                float z3 = gelu_f(c[mt][nt][3] + b1r[nt * 2 + 1]);
                *(float2*)&sm[Z_O + row * 132 + col]       = make_float2(tf32f(z0), tf32f(z1));
                *(float2*)&sm[Z_O + (row + 8) * 132 + col] = make_float2(tf32f(z2), tf32f(z3));
            }
        __syncthreads();

        // ======== MLP2: C = Z1 @ W2  (K=128) ========
#pragma unroll
        for (int mt = 0; mt < 2; mt++)
#pragma unroll
            for (int nt = 0; nt < 8; nt++)
#pragma unroll
                for (int i = 0; i < 4; i++) c[mt][nt][i] = 0.f;
        {
            const float* As = &sm[Z_O + (mb + lr) * 132 + lc];
            const float* Bs = &sm[W2_O + lc * 132 + nb + lr];
#pragma unroll 4
            for (int kt = 0; kt < 16; kt++) {
                uint32_t a[2][4], bf[8][2];
#pragma unroll
                for (int mt = 0; mt < 2; mt++) {
                    const float* p = As + mt * 16 * 132 + kt * 8;
                    a[mt][0] = __float_as_uint(p[0]);
                    a[mt][1] = __float_as_uint(p[8 * 132]);
                    a[mt][2] = __float_as_uint(p[4]);
                    a[mt][3] = __float_as_uint(p[8 * 132 + 4]);
                }
#pragma unroll
                for (int nt = 0; nt < 8; nt++) {
                    const float* p = Bs + kt * 8 * 132 + nt * 8;
                    bf[nt][0] = __float_as_uint(p[0]);
                    bf[nt][1] = __float_as_uint(p[4 * 132]);
                }
#pragma unroll
                for (int mt = 0; mt < 2; mt++)
#pragma unroll
                    for (int nt = 0; nt < 8; nt++) mma8(c[mt][nt], a[mt], bf[nt]);
            }
        }
        __syncthreads();

        // epilogue 2: Z = gelu(C + b2); S += columns
#pragma unroll
        for (int mt = 0; mt < 2; mt++)
#pragma unroll
            for (int nt = 0; nt < 8; nt++) {
                int row = mb + mt * 16 + lr;
                int col = nb + nt * 8 + 2 * lc;
                float z0 = gelu_f(c[mt][nt][0] + b2r[nt * 2]);
                float z1 = gelu_f(c[mt][nt][1] + b2r[nt * 2 + 1]);
                float z2 = gelu_f(c[mt][nt][2] + b2r[nt * 2]);
                float z3 = gelu_f(c[mt][nt][3] + b2r[nt * 2 + 1]);
                sacc[nt * 2]     += z0 + z2;
                sacc[nt * 2 + 1] += z1 + z3;
                *(float2*)&sm[Z_O + row * 132 + col]       = make_float2(tf32f(z0), tf32f(z1));
                *(float2*)&sm[Z_O + (row + 8) * 132 + col] = make_float2(tf32f(z2), tf32f(z3));
            }
        __syncthreads();

        // ======== Gram: G += Z^T @ Z ========
        {
#pragma unroll 4
            for (int kt = 0; kt < 16; kt++) {
                uint32_t a[2][4], bf[8][2];
                const float* At = &sm[Z_O + (kt * 8 + lc) * 132 + mb + lr];
#pragma unroll
                for (int mt = 0; mt < 2; mt++) {
                    const float* p = At + mt * 16;
                    a[mt][0] = __float_as_uint(p[0]);
                    a[mt][1] = __float_as_uint(p[8]);
                    a[mt][2] = __float_as_uint(p[4 * 132]);
                    a[mt][3] = __float_as_uint(p[4 * 132 + 8]);
                }
                const float* Bt = &sm[Z_O + (kt * 8 + lc) * 132 + nb + lr];
#pragma unroll
                for (int nt = 0; nt < 8; nt++) {
                    const float* p = Bt + nt * 8;
                    bf[nt][0] = __float_as_uint(p[0]);
                    bf[nt][1] = __float_as_uint(p[4 * 132]);
                }
#pragma unroll
                for (int mt = 0; mt < 2; mt++)
#pragma unroll
                    for (int nt = 0; nt < 8; nt++) mma8(g[mt][nt], a[mt], bf[nt]);
            }
        }
        __syncthreads();
    }

    // ---- contract G with a_h in-register: v_h[col] = sum_rows a_h[row]*G[row][col] ----
    {
        float ar0[2][2], ar1[2][2];
#pragma unroll
        for (int mt = 0; mt < 2; mt++) {
            int row = mb + mt * 16 + lr;
            ar0[mt][0] = sm[SA0_O + row];     ar0[mt][1] = sm[SA0_O + row + 8];
            ar1[mt][0] = sm[SA1_O + row];     ar1[mt][1] = sm[SA1_O + row + 8];
        }
        float v0[16], v1[16];
#pragma unroll
        for (int nt = 0; nt < 8; nt++)
#pragma unroll
            for (int j = 0; j < 2; j++) {
                float s0 = 0.f, s1 = 0.f;
#pragma unroll
                for (int mt = 0; mt < 2; mt++) {
                    s0 = fmaf(ar0[mt][0], g[mt][nt][j],     s0);
                    s0 = fmaf(ar0[mt][1], g[mt][nt][2 + j], s0);
                    s1 = fmaf(ar1[mt][0], g[mt][nt][j],     s1);
                    s1 = fmaf(ar1[mt][1], g[mt][nt][2 + j], s1);
                }
                v0[nt * 2 + j] = s0; v1[nt * 2 + j] = s1;
            }
        // reduce across lr (lanes lc, lc+4, ..., lc+28)
#pragma unroll
        for (int i = 0; i < 16; i++) {
            v0[i] += __shfl_down_sync(0xFFFFFFFFu, v0[i], 16);
            v0[i] += __shfl_down_sync(0xFFFFFFFFu, v0[i], 8);
            v0[i] += __shfl_down_sync(0xFFFFFFFFu, v0[i], 4);
            v1[i] += __shfl_down_sync(0xFFFFFFFFu, v1[i], 16);
            v1[i] += __shfl_down_sync(0xFFFFFFFFu, v1[i], 8);
            v1[i] += __shfl_down_sync(0xFFFFFFFFu, v1[i], 4);
        }
        if (lr == 0) {
#pragma unroll
            for (int i = 0; i < 16; i++) {
                int col = nb + (i >> 1) * 8 + 2 * lc + (i & 1);
                atomicAdd(&sm[SV_O + col],       v0[i]);
                atomicAdd(&sm[SV_O + 128 + col], v1[i]);
            }
        }
    }

    // ---- reduce S ----
#pragma unroll
    for (int i = 0; i < 16; i++) {
        float v = sacc[i];
        v += __shfl_down_sync(0xFFFFFFFFu, v, 16);
        v += __shfl_down_sync(0xFFFFFFFFu, v, 8);
        v += __shfl_down_sync(0xFFFFFFFFu, v, 4);
        if (lr == 0) atomicAdd(&sm[SS_O + nb + (i >> 1) * 8 + 2 * lc + (i & 1)], v);
    }
    __syncthreads();
    if (tid < 128) g_partS[bid][tid] = sm[SS_O + tid];
    g_partV[bid][tid] = sm[SV_O + tid];
}

// ================= tail: tiny reduce + factorized attention =================
__global__ void tail_kernel(const float* __restrict__ embed,
                            const float* __restrict__ Wq, const float* __restrict__ bq,
                            const float* __restrict__ Wk, const float* __restrict__ bk,
                            const float* __restrict__ Wv, const float* __restrict__ bv,
                            const float* __restrict__ Wo, const float* __restrict__ bo,
                            float* __restrict__ out)
{
    __shared__ float sqf[DD], sa0[DD], sa1[DD], ss[DD], sm0[DD], sm1[DD], sattn[DD];
    const int t = threadIdx.x;
    const int b = blockIdx.x;

    ss[t]  = g_partS[b*4][t] + g_partS[b*4+1][t] + g_partS[b*4+2][t] + g_partS[b*4+3][t];
    sm0[t] = g_partV[b*4][t] + g_partV[b*4+1][t] + g_partV[b*4+2][t] + g_partV[b*4+3][t];
    sm1[t] = g_partV[b*4][128+t] + g_partV[b*4+1][128+t] + g_partV[b*4+2][128+t] + g_partV[b*4+3][128+t];

    float acc = bq[t];
#pragma unroll 8
    for (int p = 0; p < DD; p++) acc = fmaf(embed[p], Wq[p * DD + t], acc);
    sqf[t] = acc;
    __syncthreads();

    float a0 = 0.f, a1 = 0.f;
#pragma unroll 8
    for (int d = 0; d < 64; d++) {
        a0 = fmaf(sqf[d],      Wk[t * DD + d],      a0);
        a1 = fmaf(sqf[64 + d], Wk[t * DD + 64 + d], a1);
    }
    sa0[t] = a0; sa1[t] = a1;
    __syncthreads();

    float asd0 = 0.f, asd1 = 0.f;
#pragma unroll 8
    for (int p = 0; p < DD; p++) {
        asd0 = fmaf(sa0[p], ss[p], asd0);
        asd1 = fmaf(sa1[p], ss[p], asd1);
    }
    float qbk0 = 0.f, qbk1 = 0.f;
#pragma unroll 8
    for (int d = 0; d < 64; d++) {
        qbk0 = fmaf(sqf[d],      bk[d],      qbk0);
        qbk1 = fmaf(sqf[64 + d], bk[64 + d], qbk1);
    }

    const int h = t >> 6;
    const float* smh = h ? sm1 : sm0;
    float dotm = 0.f, swv = 0.f;
#pragma unroll 8
    for (int q = 0; q < DD; q++) {
        float wv = Wv[q * DD + t];
        dotm = fmaf(smh[q], wv, dotm);
        swv  = fmaf(ss[q],  wv, swv);
    }
    float asd = h ? asd1 : asd0;
    float qbk = h ? qbk1 : qbk0;
    float attn = (dotm + asd * bv[t] + qbk * (swv + (float)NN * bv[t])) * (1.0f / (float)NN);
    sattn[t] = attn;
    __syncthreads();

    float o = bo[t];
#pragma unroll 8
    for (int i = 0; i < DD; i++) o = fmaf(sattn[i], Wo[i * DD + t], o);
    out[b * DD + t] = o;
}

// ================= launch =================
extern "C" void kernel_launch(void* const* d_in, const int* in_sizes, int n_in,
                              void* d_out, int out_size)
{
    const float* u     = (const float*)d_in[0];
    const float* W1    = (const float*)d_in[2];
    const float* b1    = (const float*)d_in[3];
    const float* W2    = (const float*)d_in[4];
    const float* b2    = (const float*)d_in[5];
    const float* embed = (const float*)d_in[6];
    const float* Wq    = (const float*)d_in[7];
    const float* bq    = (const float*)d_in[8];
    const float* Wk    = (const float*)d_in[9];
    const float* bk    = (const float*)d_in[10];
    const float* Wv    = (const float*)d_in[11];
    const float* bv    = (const float*)d_in[12];
    const float* Wo    = (const float*)d_in[13];
    const float* bo    = (const float*)d_in[14];
    float* out = (float*)d_out;

    cudaFuncSetAttribute(fused_mma_kernel,
                         cudaFuncAttributeMaxDynamicSharedMemorySize, SMEM_BYTES);

    fused_mma_kernel<<<NBLK, 256, SMEM_BYTES>>>(u, W1, b1, W2, b2, embed, Wq, bq, Wk);
    tail_kernel<<<BB, 128>>>(embed, Wq, bq, Wk, bk, Wv, bv, Wo, bo, out);
}